// round 3
// baseline (speedup 1.0000x reference)
#include <cuda_runtime.h>
#include <cuda_bf16.h>
#include <cstdint>

#define N_USERS   100000
#define N_NODES   150000
#define EMB_DIM   64
#define VPR       16            // float4 per node row
#define N_LAYERS  3
#define MAXE      2000000
#define SCAN_CHUNK 1024
#define SCAN_BLOCKS ((N_NODES + SCAN_CHUNK - 1) / SCAN_CHUNK)  // 147

// ------------- static scratch (no allocations allowed) -----------------------
__device__ int   g_is64;
__device__ int   g_idx[2 * MAXE];             // int32 row[0..E) ++ col[E..2E)
__device__ int   g_hist[N_NODES];
__device__ int   g_cursor[N_NODES];
__device__ int   g_off[N_NODES + 1];
__device__ int   g_part[SCAN_BLOCKS];
__device__ float g_dis[N_NODES];              // deg_inv_sqrt
__device__ int   g_src[MAXE];                 // CSR: source node per sorted edge
__device__ float g_w[MAXE];                   // CSR: norm per sorted edge
__device__ float g_xa[(size_t)N_NODES * EMB_DIM];
__device__ float g_xb[(size_t)N_NODES * EMB_DIM];

// ------------- dtype detection + conversion ----------------------------------
// If edge_index is really int64, the first 256 values are all in [0, N_NODES).
// If it is int32 read as int64, values pack two ids -> >= 2^32 almost surely.
__global__ void k_detect(const long long* __restrict__ ei) {
    if (blockIdx.x == 0 && threadIdx.x == 0) {
        int ok = 1;
        for (int i = 0; i < 256; i++) {
            long long v = ei[i];
            if (v < 0 || v >= N_NODES) { ok = 0; break; }
        }
        g_is64 = ok;
    }
}

__global__ void k_convert(const void* __restrict__ ei, int n) {   // n = 2*E
    int i = blockIdx.x * blockDim.x + threadIdx.x;
    if (i >= n) return;
    long long v;
    if (g_is64) v = ((const long long*)ei)[i];
    else        v = (long long)((const int*)ei)[i];
    // defensive clamp: never trap, let correctness check catch logic errors
    if (v < 0) v = 0;
    if (v >= N_NODES) v = N_NODES - 1;
    g_idx[i] = (int)v;
}

// ------------- setup kernels -------------------------------------------------

__global__ void k_zero2() {
    int i = blockIdx.x * blockDim.x + threadIdx.x;
    if (i < N_NODES) { g_hist[i] = 0; g_cursor[i] = 0; }
}

__global__ void k_hist(int E) {
    int e = blockIdx.x * blockDim.x + threadIdx.x;
    if (e < E) atomicAdd(&g_hist[g_idx[E + e]], 1);   // col = g_idx[E..2E)
}

__global__ void k_dis() {
    int i = blockIdx.x * blockDim.x + threadIdx.x;
    if (i < N_NODES) {
        int h = g_hist[i];
        g_dis[i] = (h > 0) ? rsqrtf((float)h) : 0.0f;
    }
}

// --- 3-pass exclusive scan of g_hist -> g_off --------------------------------
__global__ void k_partials() {
    __shared__ int s[SCAN_CHUNK];
    int idx = blockIdx.x * SCAN_CHUNK + threadIdx.x;
    s[threadIdx.x] = (idx < N_NODES) ? g_hist[idx] : 0;
    __syncthreads();
    for (int o = SCAN_CHUNK / 2; o > 0; o >>= 1) {
        if (threadIdx.x < o) s[threadIdx.x] += s[threadIdx.x + o];
        __syncthreads();
    }
    if (threadIdx.x == 0) g_part[blockIdx.x] = s[0];
}

__global__ void k_scanpart() {
    if (threadIdx.x == 0) {
        int run = 0;
        for (int b = 0; b < SCAN_BLOCKS; b++) {
            int v = g_part[b];
            g_part[b] = run;
            run += v;
        }
    }
}

__global__ void k_scanfinal() {
    __shared__ int s[SCAN_CHUNK];
    int t = threadIdx.x;
    int idx = blockIdx.x * SCAN_CHUNK + t;
    int val = (idx < N_NODES) ? g_hist[idx] : 0;
    s[t] = val;
    __syncthreads();
    for (int o = 1; o < SCAN_CHUNK; o <<= 1) {
        int v = (t >= o) ? s[t - o] : 0;
        __syncthreads();
        s[t] += v;
        __syncthreads();
    }
    int incl = s[t];
    int base = g_part[blockIdx.x];
    if (idx < N_NODES)      g_off[idx] = base + incl - val;
    if (idx == N_NODES - 1) g_off[N_NODES] = base + incl;
}

// --- place edges into CSR ----------------------------------------------------
__global__ void k_place(int E) {
    int e = blockIdx.x * blockDim.x + threadIdx.x;
    if (e >= E) return;
    int r = g_idx[e];
    int c = g_idx[E + e];
    int p = g_off[c] + atomicAdd(&g_cursor[c], 1);
    g_src[p] = r;
    g_w[p]   = g_dis[r] * g_dis[c];
}

// x0 = emb, acc = emb
__global__ void k_init(const float4* __restrict__ emb, float4* __restrict__ acc) {
    int i = blockIdx.x * blockDim.x + threadIdx.x;
    if (i < N_NODES * VPR) {
        float4 v = emb[i];
        ((float4*)g_xa)[i] = v;
        acc[i] = v;
    }
}

// ------------- main gather layer (atomic-free) -------------------------------
// 16 threads per destination node; each lane owns one float4 of the 64-dim row.
__global__ void __launch_bounds__(256)
k_gather(int a_to_b, float4* __restrict__ acc, float scale) {
    int gid  = blockIdx.x * blockDim.x + threadIdx.x;
    int node = gid >> 4;
    int lane = gid & 15;
    if (node >= N_NODES) return;

    const float4* __restrict__ x  = a_to_b ? (const float4*)g_xa : (const float4*)g_xb;
    float4*       __restrict__ xn = a_to_b ? (float4*)g_xb       : (float4*)g_xa;

    int s = g_off[node];
    int e = g_off[node + 1];

    float4 r = make_float4(0.f, 0.f, 0.f, 0.f);
    for (int p = s; p < e; p++) {
        int   src = g_src[p];
        float w   = g_w[p];
        float4 v = __ldg(&x[src * VPR + lane]);
        r.x += w * v.x;
        r.y += w * v.y;
        r.z += w * v.z;
        r.w += w * v.w;
    }

    int idx = node * VPR + lane;
    xn[idx] = r;
    float4 a = acc[idx];
    a.x = (a.x + r.x) * scale;
    a.y = (a.y + r.y) * scale;
    a.z = (a.z + r.z) * scale;
    a.w = (a.w + r.w) * scale;
    acc[idx] = a;
}

// ------------- launch --------------------------------------------------------

extern "C" void kernel_launch(void* const* d_in, const int* in_sizes, int n_in,
                              void* d_out, int out_size) {
    const void*  ei  = d_in[0];
    const float* emb = (const float*)d_in[1];
    const int E = in_sizes[0] / 2;

    float4* acc = (float4*)d_out;

    const int T = 256;
    const int nodeBlocks = (N_NODES + T - 1) / T;
    const int edgeBlocks = (E + T - 1) / T;
    const int emb2Blocks = (2 * E + T - 1) / T;
    const int embBlocks  = (N_NODES * VPR + T - 1) / T;

    // dtype detect + index conversion to int32
    k_detect<<<1, 32>>>((const long long*)ei);
    k_convert<<<emb2Blocks, T>>>(ei, 2 * E);

    // degree histogram + deg_inv_sqrt
    k_zero2<<<nodeBlocks, T>>>();
    k_hist<<<edgeBlocks, T>>>(E);
    k_dis<<<nodeBlocks, T>>>();

    // exclusive scan -> g_off
    k_partials<<<SCAN_BLOCKS, SCAN_CHUNK>>>();
    k_scanpart<<<1, 32>>>();
    k_scanfinal<<<SCAN_BLOCKS, SCAN_CHUNK>>>();

    // CSR placement with per-edge norm
    k_place<<<edgeBlocks, T>>>(E);

    // x0 and accumulator init
    k_init<<<embBlocks, T>>>((const float4*)emb, acc);

    // 3 propagation layers, atomic-free gather, accumulator fused
    for (int layer = 0; layer < N_LAYERS; layer++) {
        float scale = (layer == N_LAYERS - 1) ? (1.0f / (N_LAYERS + 1)) : 1.0f;
        k_gather<<<embBlocks, T>>>((layer % 2 == 0) ? 1 : 0, acc, scale);
    }
}

// round 4
// speedup vs baseline: 1.3500x; 1.3500x over previous
#include <cuda_runtime.h>
#include <cuda_bf16.h>
#include <cuda_fp16.h>
#include <cstdint>

#define N_USERS   100000
#define N_NODES   150000
#define EMB_DIM   64
#define VPR       16            // 4-element granules per node row
#define N_LAYERS  3
#define MAXE      2000000
#define SCAN_CHUNK 1024
#define SCAN_BLOCKS ((N_NODES + SCAN_CHUNK - 1) / SCAN_CHUNK)  // 147

// ------------- static scratch (no allocations allowed) -----------------------
__device__ int    g_is64;
__device__ int    g_idx[2 * MAXE];            // int32 row[0..E) ++ col[E..2E)
__device__ int    g_hist[N_NODES];
__device__ int    g_cursor[N_NODES];
__device__ int    g_off[N_NODES + 1];
__device__ int    g_part[SCAN_BLOCKS];
__device__ float  g_dis[N_NODES];             // deg_inv_sqrt
__device__ int2   g_csr[MAXE];                // (src, __float_as_int(norm))
// half-precision propagation buffers: 64 halves (128 B) per node row
__device__ __half g_x0[(size_t)N_NODES * EMB_DIM];
__device__ __half g_x1[(size_t)N_NODES * EMB_DIM];
__device__ __half g_x2[(size_t)N_NODES * EMB_DIM];
__device__ __half g_x3[(size_t)N_NODES * EMB_DIM];

// ------------- dtype detection ------------------------------------------------
__global__ void k_detect(const long long* __restrict__ ei) {
    if (threadIdx.x == 0) {
        int ok = 1;
        for (int i = 0; i < 256; i++) {
            long long v = ei[i];
            if (v < 0 || v >= N_NODES) { ok = 0; break; }
        }
        g_is64 = ok;
    }
}

__global__ void k_zero2() {
    int i = blockIdx.x * blockDim.x + threadIdx.x;
    if (i < N_NODES) { g_hist[i] = 0; g_cursor[i] = 0; }
}

// convert indices to int32 AND build degree histogram of col in one pass
__global__ void k_conv_hist(const void* __restrict__ ei, int E) {
    int i = blockIdx.x * blockDim.x + threadIdx.x;
    int n = 2 * E;
    if (i >= n) return;
    long long v;
    if (g_is64) v = ((const long long*)ei)[i];
    else        v = (long long)((const int*)ei)[i];
    if (v < 0) v = 0;
    if (v >= N_NODES) v = N_NODES - 1;
    int iv = (int)v;
    g_idx[i] = iv;
    if (i >= E) atomicAdd(&g_hist[iv], 1);    // col half
}

__global__ void k_dis() {
    int i = blockIdx.x * blockDim.x + threadIdx.x;
    if (i < N_NODES) {
        int h = g_hist[i];
        g_dis[i] = (h > 0) ? rsqrtf((float)h) : 0.0f;
    }
}

// --- 3-pass exclusive scan of g_hist -> g_off --------------------------------
__global__ void k_partials() {
    __shared__ int s[SCAN_CHUNK];
    int idx = blockIdx.x * SCAN_CHUNK + threadIdx.x;
    s[threadIdx.x] = (idx < N_NODES) ? g_hist[idx] : 0;
    __syncthreads();
    for (int o = SCAN_CHUNK / 2; o > 0; o >>= 1) {
        if (threadIdx.x < o) s[threadIdx.x] += s[threadIdx.x + o];
        __syncthreads();
    }
    if (threadIdx.x == 0) g_part[blockIdx.x] = s[0];
}

__global__ void k_scanpart() {
    if (threadIdx.x == 0) {
        int run = 0;
        for (int b = 0; b < SCAN_BLOCKS; b++) {
            int v = g_part[b];
            g_part[b] = run;
            run += v;
        }
    }
}

__global__ void k_scanfinal() {
    __shared__ int s[SCAN_CHUNK];
    int t = threadIdx.x;
    int idx = blockIdx.x * SCAN_CHUNK + t;
    int val = (idx < N_NODES) ? g_hist[idx] : 0;
    s[t] = val;
    __syncthreads();
    for (int o = 1; o < SCAN_CHUNK; o <<= 1) {
        int v = (t >= o) ? s[t - o] : 0;
        __syncthreads();
        s[t] += v;
        __syncthreads();
    }
    int incl = s[t];
    int base = g_part[blockIdx.x];
    if (idx < N_NODES)      g_off[idx] = base + incl - val;
    if (idx == N_NODES - 1) g_off[N_NODES] = base + incl;
}

// --- place edges into CSR (single 8B store per edge) -------------------------
__global__ void k_place(int E) {
    int e = blockIdx.x * blockDim.x + threadIdx.x;
    if (e >= E) return;
    int r = g_idx[e];
    int c = g_idx[E + e];
    int p = g_off[c] + atomicAdd(&g_cursor[c], 1);
    float w = g_dis[r] * g_dis[c];
    g_csr[p] = make_int2(r, __float_as_int(w));
}

// x0(half) = emb
__global__ void k_init(const float4* __restrict__ emb) {
    int i = blockIdx.x * blockDim.x + threadIdx.x;
    if (i >= N_NODES * VPR) return;
    float4 v = emb[i];
    __half2 h0 = __floats2half2_rn(v.x, v.y);
    __half2 h1 = __floats2half2_rn(v.z, v.w);
    uint2 packed;
    packed.x = *(unsigned int*)&h0;
    packed.y = *(unsigned int*)&h1;
    ((uint2*)g_x0)[i] = packed;
}

// ------------- main gather layer (atomic-free, half in/out, fp32 accum) ------
// 16 threads per destination node; each lane owns 4 halves (8 B) of the row.
__global__ void __launch_bounds__(256)
k_gather(const __half* __restrict__ xin, __half* __restrict__ xout) {
    int gid  = blockIdx.x * blockDim.x + threadIdx.x;
    int node = gid >> 4;
    int lane = gid & 15;
    if (node >= N_NODES) return;

    const uint2* __restrict__ x = (const uint2*)xin;

    int s = g_off[node];
    int e = g_off[node + 1];

    float4 r = make_float4(0.f, 0.f, 0.f, 0.f);
    for (int p = s; p < e; p++) {
        int2  ed = __ldg(&g_csr[p]);          // broadcast within 16-lane group
        float w  = __int_as_float(ed.y);
        uint2 v  = __ldg(&x[ed.x * VPR + lane]);
        __half2 h0 = *(__half2*)&v.x;
        __half2 h1 = *(__half2*)&v.y;
        float2 f0 = __half22float2(h0);
        float2 f1 = __half22float2(h1);
        r.x = fmaf(w, f0.x, r.x);
        r.y = fmaf(w, f0.y, r.y);
        r.z = fmaf(w, f1.x, r.z);
        r.w = fmaf(w, f1.y, r.w);
    }

    __half2 o0 = __floats2half2_rn(r.x, r.y);
    __half2 o1 = __floats2half2_rn(r.z, r.w);
    uint2 packed;
    packed.x = *(unsigned int*)&o0;
    packed.y = *(unsigned int*)&o1;
    ((uint2*)xout)[node * VPR + lane] = packed;
}

// ------------- final combine: out = (emb + x1 + x2 + x3) / 4 -----------------
__global__ void k_combine(const float4* __restrict__ emb, float4* __restrict__ out) {
    int i = blockIdx.x * blockDim.x + threadIdx.x;
    if (i >= N_NODES * VPR) return;
    float4 a = emb[i];
    uint2 p1 = ((const uint2*)g_x1)[i];
    uint2 p2 = ((const uint2*)g_x2)[i];
    uint2 p3 = ((const uint2*)g_x3)[i];
    float2 b0 = __half22float2(*(__half2*)&p1.x);
    float2 b1 = __half22float2(*(__half2*)&p1.y);
    float2 c0 = __half22float2(*(__half2*)&p2.x);
    float2 c1 = __half22float2(*(__half2*)&p2.y);
    float2 d0 = __half22float2(*(__half2*)&p3.x);
    float2 d1 = __half22float2(*(__half2*)&p3.y);
    a.x = (a.x + b0.x + c0.x + d0.x) * 0.25f;
    a.y = (a.y + b0.y + c0.y + d0.y) * 0.25f;
    a.z = (a.z + b1.x + c1.x + d1.x) * 0.25f;
    a.w = (a.w + b1.y + c1.y + d1.y) * 0.25f;
    out[i] = a;
}

// ------------- launch --------------------------------------------------------

extern "C" void kernel_launch(void* const* d_in, const int* in_sizes, int n_in,
                              void* d_out, int out_size) {
    const void*  ei  = d_in[0];
    const float* emb = (const float*)d_in[1];
    const int E = in_sizes[0] / 2;

    const int T = 256;
    const int nodeBlocks = (N_NODES + T - 1) / T;
    const int edgeBlocks = (E + T - 1) / T;
    const int e2Blocks   = (2 * E + T - 1) / T;
    const int embBlocks  = (N_NODES * VPR + T - 1) / T;

    k_detect<<<1, 32>>>((const long long*)ei);
    k_zero2<<<nodeBlocks, T>>>();
    k_conv_hist<<<e2Blocks, T>>>(ei, E);
    k_dis<<<nodeBlocks, T>>>();

    k_partials<<<SCAN_BLOCKS, SCAN_CHUNK>>>();
    k_scanpart<<<1, 32>>>();
    k_scanfinal<<<SCAN_BLOCKS, SCAN_CHUNK>>>();

    k_place<<<edgeBlocks, T>>>(E);
    k_init<<<embBlocks, T>>>((const float4*)emb);

    __half *x0, *x1, *x2, *x3;
    cudaGetSymbolAddress((void**)&x0, g_x0);
    cudaGetSymbolAddress((void**)&x1, g_x1);
    cudaGetSymbolAddress((void**)&x2, g_x2);
    cudaGetSymbolAddress((void**)&x3, g_x3);

    k_gather<<<embBlocks, T>>>(x0, x1);
    k_gather<<<embBlocks, T>>>(x1, x2);
    k_gather<<<embBlocks, T>>>(x2, x3);

    k_combine<<<embBlocks, T>>>((const float4*)emb, (float4*)d_out);
}

// round 5
// speedup vs baseline: 1.5139x; 1.1214x over previous
#include <cuda_runtime.h>
#include <cuda_bf16.h>
#include <cuda_fp16.h>
#include <cstdint>

#define N_USERS   100000
#define N_NODES   150000
#define EMB_DIM   64
#define LPN       8             // lanes per node (each lane: 8 halves = 16 B)
#define N_LAYERS  3
#define MAXE      2000000
#define SCAN_CHUNK 1024
#define SCAN_BLOCKS ((N_NODES + SCAN_CHUNK - 1) / SCAN_CHUNK)  // 147

// ------------- static scratch (no allocations allowed) -----------------------
__device__ int    g_is64;
__device__ int    g_idx[2 * MAXE];            // int32 row[0..E) ++ col[E..2E)
__device__ int    g_hist[N_NODES];
__device__ int    g_cursor[N_NODES];
__device__ int    g_off[N_NODES + 1];
__device__ int    g_part[SCAN_BLOCKS];
__device__ float  g_dis[N_NODES];             // deg_inv_sqrt
__device__ int2   g_csr[MAXE];                // (src, __float_as_int(norm))
// half-precision propagation buffers: 64 halves (128 B) per node row
__device__ __half g_x0[(size_t)N_NODES * EMB_DIM];
__device__ __half g_x1[(size_t)N_NODES * EMB_DIM];
__device__ __half g_x2[(size_t)N_NODES * EMB_DIM];

// ------------- helpers --------------------------------------------------------
__device__ __forceinline__ void fma8(float* acc, float w, uint4 v) {
    __half2 h0 = *(__half2*)&v.x;
    __half2 h1 = *(__half2*)&v.y;
    __half2 h2 = *(__half2*)&v.z;
    __half2 h3 = *(__half2*)&v.w;
    float2 f0 = __half22float2(h0);
    float2 f1 = __half22float2(h1);
    float2 f2 = __half22float2(h2);
    float2 f3 = __half22float2(h3);
    acc[0] = fmaf(w, f0.x, acc[0]);
    acc[1] = fmaf(w, f0.y, acc[1]);
    acc[2] = fmaf(w, f1.x, acc[2]);
    acc[3] = fmaf(w, f1.y, acc[3]);
    acc[4] = fmaf(w, f2.x, acc[4]);
    acc[5] = fmaf(w, f2.y, acc[5]);
    acc[6] = fmaf(w, f3.x, acc[6]);
    acc[7] = fmaf(w, f3.y, acc[7]);
}

// ------------- dtype detection ------------------------------------------------
__global__ void k_detect(const long long* __restrict__ ei) {
    if (threadIdx.x == 0) {
        int ok = 1;
        for (int i = 0; i < 256; i++) {
            long long v = ei[i];
            if (v < 0 || v >= N_NODES) { ok = 0; break; }
        }
        g_is64 = ok;
    }
}

__global__ void k_zero2() {
    int i = blockIdx.x * blockDim.x + threadIdx.x;
    if (i < N_NODES) { g_hist[i] = 0; g_cursor[i] = 0; }
}

// convert indices to int32 AND build degree histogram of col in one pass
__global__ void k_conv_hist(const void* __restrict__ ei, int E) {
    int i = blockIdx.x * blockDim.x + threadIdx.x;
    int n = 2 * E;
    if (i >= n) return;
    long long v;
    if (g_is64) v = ((const long long*)ei)[i];
    else        v = (long long)((const int*)ei)[i];
    if (v < 0) v = 0;
    if (v >= N_NODES) v = N_NODES - 1;
    int iv = (int)v;
    g_idx[i] = iv;
    if (i >= E) atomicAdd(&g_hist[iv], 1);    // col half
}

__global__ void k_dis() {
    int i = blockIdx.x * blockDim.x + threadIdx.x;
    if (i < N_NODES) {
        int h = g_hist[i];
        g_dis[i] = (h > 0) ? rsqrtf((float)h) : 0.0f;
    }
}

// --- 3-pass exclusive scan of g_hist -> g_off --------------------------------
__global__ void k_partials() {
    __shared__ int s[SCAN_CHUNK];
    int idx = blockIdx.x * SCAN_CHUNK + threadIdx.x;
    s[threadIdx.x] = (idx < N_NODES) ? g_hist[idx] : 0;
    __syncthreads();
    for (int o = SCAN_CHUNK / 2; o > 0; o >>= 1) {
        if (threadIdx.x < o) s[threadIdx.x] += s[threadIdx.x + o];
        __syncthreads();
    }
    if (threadIdx.x == 0) g_part[blockIdx.x] = s[0];
}

__global__ void k_scanpart() {
    if (threadIdx.x == 0) {
        int run = 0;
        for (int b = 0; b < SCAN_BLOCKS; b++) {
            int v = g_part[b];
            g_part[b] = run;
            run += v;
        }
    }
}

__global__ void k_scanfinal() {
    __shared__ int s[SCAN_CHUNK];
    int t = threadIdx.x;
    int idx = blockIdx.x * SCAN_CHUNK + t;
    int val = (idx < N_NODES) ? g_hist[idx] : 0;
    s[t] = val;
    __syncthreads();
    for (int o = 1; o < SCAN_CHUNK; o <<= 1) {
        int v = (t >= o) ? s[t - o] : 0;
        __syncthreads();
        s[t] += v;
        __syncthreads();
    }
    int incl = s[t];
    int base = g_part[blockIdx.x];
    if (idx < N_NODES)      g_off[idx] = base + incl - val;
    if (idx == N_NODES - 1) g_off[N_NODES] = base + incl;
}

// --- place edges into CSR (single 8B store per edge) -------------------------
__global__ void k_place(int E) {
    int e = blockIdx.x * blockDim.x + threadIdx.x;
    if (e >= E) return;
    int r = g_idx[e];
    int c = g_idx[E + e];
    int p = g_off[c] + atomicAdd(&g_cursor[c], 1);
    float w = g_dis[r] * g_dis[c];
    g_csr[p] = make_int2(r, __float_as_int(w));
}

// x0(half) = emb   (one thread per 4 floats)
__global__ void k_init(const float4* __restrict__ emb) {
    int i = blockIdx.x * blockDim.x + threadIdx.x;
    if (i >= N_NODES * 16) return;
    float4 v = emb[i];
    __half2 h0 = __floats2half2_rn(v.x, v.y);
    __half2 h1 = __floats2half2_rn(v.z, v.w);
    uint2 packed;
    packed.x = *(unsigned int*)&h0;
    packed.y = *(unsigned int*)&h1;
    ((uint2*)g_x0)[i] = packed;
}

// ------------- gather layer: 8 lanes/node, 16B loads, 2x unroll --------------
__global__ void __launch_bounds__(256)
k_gather(const __half* __restrict__ xin, __half* __restrict__ xout) {
    int gid  = blockIdx.x * blockDim.x + threadIdx.x;
    int node = gid >> 3;
    int lane = gid & 7;
    if (node >= N_NODES) return;

    const uint4* __restrict__ x = (const uint4*)xin;

    int s = g_off[node];
    int e = g_off[node + 1];

    float acc[8] = {0.f, 0.f, 0.f, 0.f, 0.f, 0.f, 0.f, 0.f};
    int p = s;
    for (; p + 2 <= e; p += 2) {
        int2 e0 = __ldg(&g_csr[p]);
        int2 e1 = __ldg(&g_csr[p + 1]);
        uint4 v0 = __ldg(&x[e0.x * LPN + lane]);
        uint4 v1 = __ldg(&x[e1.x * LPN + lane]);
        fma8(acc, __int_as_float(e0.y), v0);
        fma8(acc, __int_as_float(e1.y), v1);
    }
    if (p < e) {
        int2 e0 = __ldg(&g_csr[p]);
        uint4 v0 = __ldg(&x[e0.x * LPN + lane]);
        fma8(acc, __int_as_float(e0.y), v0);
    }

    __half2 o0 = __floats2half2_rn(acc[0], acc[1]);
    __half2 o1 = __floats2half2_rn(acc[2], acc[3]);
    __half2 o2 = __floats2half2_rn(acc[4], acc[5]);
    __half2 o3 = __floats2half2_rn(acc[6], acc[7]);
    uint4 packed;
    packed.x = *(unsigned int*)&o0;
    packed.y = *(unsigned int*)&o1;
    packed.z = *(unsigned int*)&o2;
    packed.w = *(unsigned int*)&o3;
    ((uint4*)xout)[node * LPN + lane] = packed;
}

// ------------- final gather fused with combine -------------------------------
// computes x3 row locally, writes out = (emb + x1 + x2 + x3)/4 in fp32
__global__ void __launch_bounds__(256)
k_gather_final(const __half* __restrict__ xin,      // x2
               const __half* __restrict__ x1h,
               const float4* __restrict__ emb,
               float4* __restrict__ out) {
    int gid  = blockIdx.x * blockDim.x + threadIdx.x;
    int node = gid >> 3;
    int lane = gid & 7;
    if (node >= N_NODES) return;

    const uint4* __restrict__ x = (const uint4*)xin;

    int s = g_off[node];
    int e = g_off[node + 1];

    float acc[8] = {0.f, 0.f, 0.f, 0.f, 0.f, 0.f, 0.f, 0.f};
    int p = s;
    for (; p + 2 <= e; p += 2) {
        int2 e0 = __ldg(&g_csr[p]);
        int2 e1 = __ldg(&g_csr[p + 1]);
        uint4 v0 = __ldg(&x[e0.x * LPN + lane]);
        uint4 v1 = __ldg(&x[e1.x * LPN + lane]);
        fma8(acc, __int_as_float(e0.y), v0);
        fma8(acc, __int_as_float(e1.y), v1);
    }
    if (p < e) {
        int2 e0 = __ldg(&g_csr[p]);
        uint4 v0 = __ldg(&x[e0.x * LPN + lane]);
        fma8(acc, __int_as_float(e0.y), v0);
    }

    // add own node's x1 and x2 rows (this lane's 8 halves each)
    uint4 a1 = ((const uint4*)x1h)[node * LPN + lane];
    uint4 a2 = x[node * LPN + lane];
    fma8(acc, 1.0f, a1);
    fma8(acc, 1.0f, a2);

    // add emb (fp32) and scale; this lane owns floats [lane*8, lane*8+8)
    int fi = node * 16 + lane * 2;
    float4 e0f = emb[fi];
    float4 e1f = emb[fi + 1];
    float4 r0, r1;
    r0.x = (e0f.x + acc[0]) * 0.25f;
    r0.y = (e0f.y + acc[1]) * 0.25f;
    r0.z = (e0f.z + acc[2]) * 0.25f;
    r0.w = (e0f.w + acc[3]) * 0.25f;
    r1.x = (e1f.x + acc[4]) * 0.25f;
    r1.y = (e1f.y + acc[5]) * 0.25f;
    r1.z = (e1f.z + acc[6]) * 0.25f;
    r1.w = (e1f.w + acc[7]) * 0.25f;
    out[fi]     = r0;
    out[fi + 1] = r1;
}

// ------------- launch --------------------------------------------------------

extern "C" void kernel_launch(void* const* d_in, const int* in_sizes, int n_in,
                              void* d_out, int out_size) {
    const void*  ei  = d_in[0];
    const float* emb = (const float*)d_in[1];
    const int E = in_sizes[0] / 2;

    const int T = 256;
    const int nodeBlocks = (N_NODES + T - 1) / T;
    const int edgeBlocks = (E + T - 1) / T;
    const int e2Blocks   = (2 * E + T - 1) / T;
    const int initBlocks = (N_NODES * 16 + T - 1) / T;
    const int gBlocks    = (N_NODES * LPN + T - 1) / T;

    k_detect<<<1, 32>>>((const long long*)ei);
    k_zero2<<<nodeBlocks, T>>>();
    k_conv_hist<<<e2Blocks, T>>>(ei, E);
    k_dis<<<nodeBlocks, T>>>();

    k_partials<<<SCAN_BLOCKS, SCAN_CHUNK>>>();
    k_scanpart<<<1, 32>>>();
    k_scanfinal<<<SCAN_BLOCKS, SCAN_CHUNK>>>();

    k_place<<<edgeBlocks, T>>>(E);
    k_init<<<initBlocks, T>>>((const float4*)emb);

    __half *x0, *x1, *x2;
    cudaGetSymbolAddress((void**)&x0, g_x0);
    cudaGetSymbolAddress((void**)&x1, g_x1);
    cudaGetSymbolAddress((void**)&x2, g_x2);

    k_gather<<<gBlocks, T>>>(x0, x1);
    k_gather<<<gBlocks, T>>>(x1, x2);
    k_gather_final<<<gBlocks, T>>>(x2, x1, (const float4*)emb, (float4*)d_out);
}